// round 3
// baseline (speedup 1.0000x reference)
#include <cuda_runtime.h>

#define RES      64
#define N_PHAL   20
#define MAX_B    256

constexpr int F4_PER_CHUNK = RES * RES * 5 / 4;   // 5120 float4 per (b,p)
constexpr int NSUB         = 4;                   // subtiles per chunk
constexpr int SUB_F4       = F4_PER_CHUNK / NSUB; // 1280 float4 = 20 KB
constexpr int SUB_POS      = SUB_F4 * 4 / 5;      // 1024 positions
constexpr int THREADS      = 256;

// Scratch: per (b,p): vf0, vf1, vs0, vs1, den
__device__ float        g_scratch[MAX_B * N_PHAL * 5];
__device__ unsigned int g_count = 0;

__device__ __forceinline__ float warp_red(float v) {
    #pragma unroll
    for (int o = 16; o > 0; o >>= 1)
        v += __shfl_down_sync(0xffffffffu, v, o);
    return v;
}

__global__ __launch_bounds__(THREADS) void fused_kernel(
    const float4* __restrict__ x, float* __restrict__ scratch,
    float* __restrict__ out)
{
    __shared__ float4 buf[2][SUB_F4];     // 2 x 20 KB double buffer
    __shared__ float  red[8][7];
    __shared__ int    s_last;

    const int chunk = blockIdx.x;         // b * N_PHAL + p
    const float4* base = x + (size_t)chunk * F4_PER_CHUNK;
    const int t = threadIdx.x;

    float A = 0.f, Bm = 0.f, C = 0.f, D = 0.f, E = 0.f, F = 0.f, den = 0.f;

    // prefetch subtile 0 into registers
    float4 r0 = base[0 * THREADS + t];
    float4 r1 = base[1 * THREADS + t];
    float4 r2 = base[2 * THREADS + t];
    float4 r3 = base[3 * THREADS + t];
    float4 r4 = base[4 * THREADS + t];

    #pragma unroll
    for (int s = 0; s < NSUB; ++s) {
        float4* bc = buf[s & 1];
        bc[0 * THREADS + t] = r0;
        bc[1 * THREADS + t] = r1;
        bc[2 * THREADS + t] = r2;
        bc[3 * THREADS + t] = r3;
        bc[4 * THREADS + t] = r4;

        if (s < NSUB - 1) {               // LDGs in flight during compute below
            const float4* nb = base + (s + 1) * SUB_F4;
            r0 = nb[0 * THREADS + t];
            r1 = nb[1 * THREADS + t];
            r2 = nb[2 * THREADS + t];
            r3 = nb[3 * THREADS + t];
            r4 = nb[4 * THREADS + t];
        }
        __syncthreads();                  // single barrier per stage (safe: see analysis)

        // one group of 4 positions per thread; 5 x LDS.128 @80B stride: conflict-free
        float4 v0 = bc[t * 5 + 0];
        float4 v1 = bc[t * 5 + 1];
        float4 v2 = bc[t * 5 + 2];
        float4 v3 = bc[t * 5 + 3];
        float4 v4 = bc[t * 5 + 4];

        int pos0 = s * SUB_POS + t * 4;   // first global position of group
        float fi  = (float)(pos0 >> 6);   // row (4 | 64 -> same for group)
        float fj0 = (float)(pos0 & 63);   // first column

        // p0: f0=v0.x f1=v0.y m=v0.z d0=v0.w d1=v1.x
        { float m = v0.z, am = fabsf(m), sc = m * am;
          float t0 = sc * v0.x, t1 = sc * v0.y;
          A  = fmaf(t1, v0.w, A);  Bm = fmaf(t0, v0.w, Bm);
          C  = fmaf(t1, v1.x, C);  D  = fmaf(t0, v1.x, D);
          E  = fmaf(am, fi, E);    F  = fmaf(am, fj0, F);
          den += am; }
        // p1: f0=v1.y f1=v1.z m=v1.w d0=v2.x d1=v2.y
        { float m = v1.w, am = fabsf(m), sc = m * am;
          float t0 = sc * v1.y, t1 = sc * v1.z;
          A  = fmaf(t1, v2.x, A);  Bm = fmaf(t0, v2.x, Bm);
          C  = fmaf(t1, v2.y, C);  D  = fmaf(t0, v2.y, D);
          E  = fmaf(am, fi, E);    F  = fmaf(am, fj0 + 1.f, F);
          den += am; }
        // p2: f0=v2.z f1=v2.w m=v3.x d0=v3.y d1=v3.z
        { float m = v3.x, am = fabsf(m), sc = m * am;
          float t0 = sc * v2.z, t1 = sc * v2.w;
          A  = fmaf(t1, v3.y, A);  Bm = fmaf(t0, v3.y, Bm);
          C  = fmaf(t1, v3.z, C);  D  = fmaf(t0, v3.z, D);
          E  = fmaf(am, fi, E);    F  = fmaf(am, fj0 + 2.f, F);
          den += am; }
        // p3: f0=v3.w f1=v4.x m=v4.y d0=v4.z d1=v4.w
        { float m = v4.y, am = fabsf(m), sc = m * am;
          float t0 = sc * v3.w, t1 = sc * v4.x;
          A  = fmaf(t1, v4.z, A);  Bm = fmaf(t0, v4.z, Bm);
          C  = fmaf(t1, v4.w, C);  D  = fmaf(t0, v4.w, D);
          E  = fmaf(am, fi, E);    F  = fmaf(am, fj0 + 3.f, F);
          den += am; }
        // NOTE: no trailing sync needed — next stage's STS targets the other
        // buffer, and STS(b_s) at stage s+2 is ordered behind SYNC_{s+1},
        // which follows every thread's compute(b_s).
    }

    // ---- block reduction of 7 accumulators ----
    A = warp_red(A);  Bm = warp_red(Bm); C = warp_red(C); D = warp_red(D);
    E = warp_red(E);  F  = warp_red(F);  den = warp_red(den);

    int wid = t >> 5, lane = t & 31;
    if (lane == 0) {
        red[wid][0] = A;  red[wid][1] = Bm; red[wid][2] = C;
        red[wid][3] = D;  red[wid][4] = E;  red[wid][5] = F;
        red[wid][6] = den;
    }
    __syncthreads();

    if (t == 0) {
        float a = 0.f, b = 0.f, c = 0.f, d = 0.f, e = 0.f, f = 0.f, dn = 0.f;
        #pragma unroll
        for (int w = 0; w < 8; ++w) {
            a += red[w][0]; b += red[w][1]; c += red[w][2];
            d += red[w][3]; e += red[w][4]; f += red[w][5];
            dn += red[w][6];
        }
        float inv = 1.f / ((dn == 0.f) ? 1.f : dn);
        float* o = scratch + (size_t)chunk * 5;
        o[0] = (a + e) * inv;   // vf0
        o[1] = (f - b) * inv;   // vf1
        o[2] = (e - c) * inv;   // vs0
        o[3] = (d + f) * inv;   // vs1
        o[4] = dn;

        __threadfence();        // scratch visible before counter bump
        unsigned old = atomicAdd(&g_count, 1u);
        s_last = (old == gridDim.x - 1u) ? 1 : 0;
    }
    __syncthreads();

    // ---- last block assembles the (B, 21, 2) output ----
    if (s_last) {
        if (t == 0) g_count = 0;          // reset for next graph replay
        __threadfence();
        const int B = gridDim.x / N_PHAL;
        const int total = B * 42;
        for (int o = t; o < total; o += THREADS) {
            int c = o & 1;
            int r = (o >> 1) % 21;
            int b = o / 42;
            const float* sp = scratch + (size_t)b * N_PHAL * 5;

            float val;
            if (r == 0) {
                float acc = 0.f;
                #pragma unroll
                for (int k = 0; k < 5; ++k) {
                    int p = 4 * k;
                    float dn = __ldcg(sp + p * 5 + 4);
                    float vf = __ldcg(sp + p * 5 + c);
                    acc += (dn != 0.f) ? vf : 0.f;
                }
                val = acc * 0.2f;
            } else {
                int q  = r;                  // 1..20
                int iq = (q - 1) >> 2;
                int pq = 8 * iq + 4 - q;     // 4*iq + j_q
                int jq = pq - 4 * iq;
                int pn = min(pq + 1, N_PHAL - 1);
                float vs = __ldcg(sp + pq * 5 + 2 + c);
                if (jq == 3) val = vs;
                else         val = 0.5f * (vs + __ldcg(sp + pn * 5 + c));
            }
            out[o] = val;
        }
    }
}

extern "C" void kernel_launch(void* const* d_in, const int* in_sizes, int n_in,
                              void* d_out, int out_size)
{
    const float4* x = (const float4*)d_in[0];
    float* out = (float*)d_out;
    int B = in_sizes[0] / (N_PHAL * RES * RES * 5);   // 256

    float* scratch;
    cudaGetSymbolAddress((void**)&scratch, g_scratch);

    fused_kernel<<<B * N_PHAL, THREADS>>>(x, scratch, out);
}

// round 5
// speedup vs baseline: 1.0525x; 1.0525x over previous
#include <cuda_runtime.h>
#include <cstdint>

#define RES      64
#define N_PHAL   20
#define MAX_B    256

constexpr int F4_PER_CHUNK = RES * RES * 5 / 4;   // 5120 float4 per (b,p)
constexpr int NSUB         = 4;                   // subtiles per chunk
constexpr int SUB_F4       = F4_PER_CHUNK / NSUB; // 1280 float4 = 20 KB
constexpr int SUB_POS      = SUB_F4 * 4 / 5;      // 1024 positions
constexpr int THREADS      = 256;

// Scratch: per (b,p): vf0, vf1, vs0, vs1, den
__device__ float        g_scratch[MAX_B * N_PHAL * 5];
__device__ unsigned int g_count = 0;

__device__ __forceinline__ float warp_red(float v) {
    #pragma unroll
    for (int o = 16; o > 0; o >>= 1)
        v += __shfl_down_sync(0xffffffffu, v, o);
    return v;
}

__device__ __forceinline__ void cp_async16(unsigned int dst_smem, const void* src) {
    asm volatile("cp.async.cg.shared.global [%0], [%1], 16;\n"
                 :: "r"(dst_smem), "l"(src) : "memory");
}
__device__ __forceinline__ void cp_commit() {
    asm volatile("cp.async.commit_group;\n" ::: "memory");
}
template <int N>
__device__ __forceinline__ void cp_wait() {
    asm volatile("cp.async.wait_group %0;\n" :: "n"(N) : "memory");
}

__global__ __launch_bounds__(THREADS, 4) void fused_kernel(
    const float4* __restrict__ x, float* __restrict__ scratch,
    float* __restrict__ out)
{
    __shared__ float4 buf[2][SUB_F4];     // 2 x 20 KB double buffer
    __shared__ float  red[8][7];
    __shared__ int    s_last;

    const int chunk = blockIdx.x;         // b * N_PHAL + p
    const float4* base = x + (size_t)chunk * F4_PER_CHUNK;
    const int t = threadIdx.x;

    float A = 0.f, Bm = 0.f, C = 0.f, D = 0.f, E = 0.f, F = 0.f, den = 0.f;

    // smem addresses for this thread's slots in each buffer
    unsigned int sb0 = (unsigned int)__cvta_generic_to_shared(&buf[0][t]);
    unsigned int sb1 = (unsigned int)__cvta_generic_to_shared(&buf[1][t]);

    // ---- prologue: issue subtiles 0 and 1 (gmem -> smem, no data registers) ----
    #pragma unroll
    for (int k = 0; k < 5; ++k)
        cp_async16(sb0 + k * THREADS * 16, base + k * THREADS + t);
    cp_commit();
    #pragma unroll
    for (int k = 0; k < 5; ++k)
        cp_async16(sb1 + k * THREADS * 16, base + SUB_F4 + k * THREADS + t);
    cp_commit();

    #pragma unroll
    for (int s = 0; s < NSUB; ++s) {
        cp_wait<1>();                     // subtile s landed (next still in flight)
        __syncthreads();

        const float4* bc = buf[s & 1];
        // 5 x LDS.128 at 80B lane stride: conflict-free
        float4 v0 = bc[t * 5 + 0];
        float4 v1 = bc[t * 5 + 1];
        float4 v2 = bc[t * 5 + 2];
        float4 v3 = bc[t * 5 + 3];
        float4 v4 = bc[t * 5 + 4];

        int pos0 = s * SUB_POS + t * 4;   // first global position of group
        float fi  = (float)(pos0 >> 6);   // row (4 | 64 -> same for group)
        float fj0 = (float)(pos0 & 63);   // first column

        // p0: f0=v0.x f1=v0.y m=v0.z d0=v0.w d1=v1.x
        { float m = v0.z, am = fabsf(m), sc = m * am;
          float t0 = sc * v0.x, t1 = sc * v0.y;
          A  = fmaf(t1, v0.w, A);  Bm = fmaf(t0, v0.w, Bm);
          C  = fmaf(t1, v1.x, C);  D  = fmaf(t0, v1.x, D);
          E  = fmaf(am, fi, E);    F  = fmaf(am, fj0, F);
          den += am; }
        // p1: f0=v1.y f1=v1.z m=v1.w d0=v2.x d1=v2.y
        { float m = v1.w, am = fabsf(m), sc = m * am;
          float t0 = sc * v1.y, t1 = sc * v1.z;
          A  = fmaf(t1, v2.x, A);  Bm = fmaf(t0, v2.x, Bm);
          C  = fmaf(t1, v2.y, C);  D  = fmaf(t0, v2.y, D);
          E  = fmaf(am, fi, E);    F  = fmaf(am, fj0 + 1.f, F);
          den += am; }
        // p2: f0=v2.z f1=v2.w m=v3.x d0=v3.y d1=v3.z
        { float m = v3.x, am = fabsf(m), sc = m * am;
          float t0 = sc * v2.z, t1 = sc * v2.w;
          A  = fmaf(t1, v3.y, A);  Bm = fmaf(t0, v3.y, Bm);
          C  = fmaf(t1, v3.z, C);  D  = fmaf(t0, v3.z, D);
          E  = fmaf(am, fi, E);    F  = fmaf(am, fj0 + 2.f, F);
          den += am; }
        // p3: f0=v3.w f1=v4.x m=v4.y d0=v4.z d1=v4.w
        { float m = v4.y, am = fabsf(m), sc = m * am;
          float t0 = sc * v3.w, t1 = sc * v4.x;
          A  = fmaf(t1, v4.z, A);  Bm = fmaf(t0, v4.z, Bm);
          C  = fmaf(t1, v4.w, C);  D  = fmaf(t0, v4.w, D);
          E  = fmaf(am, fi, E);    F  = fmaf(am, fj0 + 3.f, F);
          den += am; }

        __syncthreads();                  // all threads done reading buf[s&1]
        if (s + 2 < NSUB) {               // refill the buffer just freed
            unsigned int sb = (s & 1) ? sb1 : sb0;
            const float4* nb = base + (s + 2) * SUB_F4;
            #pragma unroll
            for (int k = 0; k < 5; ++k)
                cp_async16(sb + k * THREADS * 16, nb + k * THREADS + t);
        }
        cp_commit();                      // commit (possibly empty) to keep count
    }

    // ---- block reduction of 7 accumulators ----
    A = warp_red(A);  Bm = warp_red(Bm); C = warp_red(C); D = warp_red(D);
    E = warp_red(E);  F  = warp_red(F);  den = warp_red(den);

    int wid = t >> 5, lane = t & 31;
    if (lane == 0) {
        red[wid][0] = A;  red[wid][1] = Bm; red[wid][2] = C;
        red[wid][3] = D;  red[wid][4] = E;  red[wid][5] = F;
        red[wid][6] = den;
    }
    __syncthreads();

    if (t == 0) {
        float a = 0.f, b = 0.f, c = 0.f, d = 0.f, e = 0.f, f = 0.f, dn = 0.f;
        #pragma unroll
        for (int w = 0; w < 8; ++w) {
            a += red[w][0]; b += red[w][1]; c += red[w][2];
            d += red[w][3]; e += red[w][4]; f += red[w][5];
            dn += red[w][6];
        }
        float inv = 1.f / ((dn == 0.f) ? 1.f : dn);
        float* o = scratch + (size_t)chunk * 5;
        o[0] = (a + e) * inv;   // vf0
        o[1] = (f - b) * inv;   // vf1
        o[2] = (e - c) * inv;   // vs0
        o[3] = (d + f) * inv;   // vs1
        o[4] = dn;

        __threadfence();        // scratch visible before counter bump
        unsigned int old = atomicAdd(&g_count, 1u);
        s_last = (old == gridDim.x - 1u) ? 1 : 0;
    }
    __syncthreads();

    // ---- last block assembles the (B, 21, 2) output ----
    if (s_last) {
        if (t == 0) g_count = 0;          // reset for next graph replay
        __threadfence();
        const int B = gridDim.x / N_PHAL;
        const int total = B * 42;
        for (int o = t; o < total; o += THREADS) {
            int c = o & 1;
            int r = (o >> 1) % 21;
            int b = o / 42;
            const float* sp = scratch + (size_t)b * N_PHAL * 5;

            float val;
            if (r == 0) {
                float acc = 0.f;
                #pragma unroll
                for (int k = 0; k < 5; ++k) {
                    int p = 4 * k;
                    float dn = __ldcg(sp + p * 5 + 4);
                    float vf = __ldcg(sp + p * 5 + c);
                    acc += (dn != 0.f) ? vf : 0.f;
                }
                val = acc * 0.2f;
            } else {
                int q  = r;                  // 1..20
                int iq = (q - 1) >> 2;
                int pq = 8 * iq + 4 - q;     // 4*iq + j_q
                int jq = pq - 4 * iq;
                int pn = min(pq + 1, N_PHAL - 1);
                float vs = __ldcg(sp + pq * 5 + 2 + c);
                if (jq == 3) val = vs;
                else         val = 0.5f * (vs + __ldcg(sp + pn * 5 + c));
            }
            out[o] = val;
        }
    }
}

extern "C" void kernel_launch(void* const* d_in, const int* in_sizes, int n_in,
                              void* d_out, int out_size)
{
    const float4* x = (const float4*)d_in[0];
    float* out = (float*)d_out;
    int B = in_sizes[0] / (N_PHAL * RES * RES * 5);   // 256

    float* scratch;
    cudaGetSymbolAddress((void**)&scratch, g_scratch);

    fused_kernel<<<B * N_PHAL, THREADS>>>(x, scratch, out);
}

// round 6
// speedup vs baseline: 1.0900x; 1.0357x over previous
#include <cuda_runtime.h>
#include <cstdint>

#define RES      64
#define N_PHAL   20
#define MAX_B    256

constexpr int F4_PER_CHUNK = RES * RES * 5 / 4;   // 5120 float4 per (b,p)
constexpr int SUB_F4       = 1280;                // 20 KB subtile (lcm of 5 and 256)
constexpr int SUB_POS      = SUB_F4 * 4 / 5;      // 1024 positions
constexpr int THREADS      = 256;
constexpr int GRID         = 592;                 // 148 SMs x 4 CTAs, persistent

// Scratch: per (b,p): vf0, vf1, vs0, vs1, den
__device__ float        g_scratch[MAX_B * N_PHAL * 5];
__device__ unsigned int g_count = 0;

__device__ __forceinline__ float warp_red(float v) {
    #pragma unroll
    for (int o = 16; o > 0; o >>= 1)
        v += __shfl_down_sync(0xffffffffu, v, o);
    return v;
}

__device__ __forceinline__ void cp_async16(unsigned int dst_smem, const void* src) {
    asm volatile("cp.async.cg.shared.global [%0], [%1], 16;\n"
                 :: "r"(dst_smem), "l"(src) : "memory");
}
__device__ __forceinline__ void cp_commit() {
    asm volatile("cp.async.commit_group;\n" ::: "memory");
}
template <int N>
__device__ __forceinline__ void cp_wait() {
    asm volatile("cp.async.wait_group %0;\n" :: "n"(N) : "memory");
}

__global__ __launch_bounds__(THREADS, 4) void fused_kernel(
    const float4* __restrict__ x, float* __restrict__ scratch,
    float* __restrict__ out, int total_chunks)
{
    __shared__ float4 buf[2][SUB_F4];     // 2 x 20 KB double buffer
    __shared__ float  red[8][7];
    __shared__ int    s_last;

    const int t   = threadIdx.x;
    const int bid = blockIdx.x;
    const int grid = gridDim.x;

    // chunks handled by this block: bid, bid+grid, ... (persistent)
    const int nchunks  = (bid < total_chunks)
                       ? (total_chunks - bid + grid - 1) / grid : 0;
    const int n_stages = nchunks * 4;

    unsigned int sb0 = (unsigned int)__cvta_generic_to_shared(&buf[0][t]);
    unsigned int sb1 = (unsigned int)__cvta_generic_to_shared(&buf[1][t]);

    // ---- issue: stage st -> chunk (bid + (st>>2)*grid), subtile (st&3) ----
    auto issue = [&](int st) {
        int ch = bid + (st >> 2) * grid;
        const float4* p = x + (size_t)ch * F4_PER_CHUNK
                            + (st & 3) * SUB_F4 + t;
        unsigned int d = (st & 1) ? sb1 : sb0;
        #pragma unroll
        for (int k = 0; k < 5; ++k)
            cp_async16(d + k * THREADS * 16, p + k * THREADS);
    };

    // prologue: two stages in flight
    if (0 < n_stages) issue(0);
    cp_commit();
    if (1 < n_stages) issue(1);
    cp_commit();

    float A = 0.f, Bm = 0.f, C = 0.f, D = 0.f, E = 0.f, F = 0.f, den = 0.f;

    for (int st = 0; st < n_stages; ++st) {
        cp_wait<1>();                     // subtile st landed (st+1 in flight)
        __syncthreads();

        const float4* bc = buf[st & 1];
        // 5 x LDS.128 at 80B lane stride: conflict-free
        float4 v0 = bc[t * 5 + 0];
        float4 v1 = bc[t * 5 + 1];
        float4 v2 = bc[t * 5 + 2];
        float4 v3 = bc[t * 5 + 3];
        float4 v4 = bc[t * 5 + 4];

        int pos0 = (st & 3) * SUB_POS + t * 4;  // position within chunk
        float fi  = (float)(pos0 >> 6);         // row (4 | 64 -> same for group)
        float fj0 = (float)(pos0 & 63);         // first column

        // p0: f0=v0.x f1=v0.y m=v0.z d0=v0.w d1=v1.x
        { float m = v0.z, am = fabsf(m), sc = m * am;
          float t0 = sc * v0.x, t1 = sc * v0.y;
          A  = fmaf(t1, v0.w, A);  Bm = fmaf(t0, v0.w, Bm);
          C  = fmaf(t1, v1.x, C);  D  = fmaf(t0, v1.x, D);
          E  = fmaf(am, fi, E);    F  = fmaf(am, fj0, F);
          den += am; }
        // p1: f0=v1.y f1=v1.z m=v1.w d0=v2.x d1=v2.y
        { float m = v1.w, am = fabsf(m), sc = m * am;
          float t0 = sc * v1.y, t1 = sc * v1.z;
          A  = fmaf(t1, v2.x, A);  Bm = fmaf(t0, v2.x, Bm);
          C  = fmaf(t1, v2.y, C);  D  = fmaf(t0, v2.y, D);
          E  = fmaf(am, fi, E);    F  = fmaf(am, fj0 + 1.f, F);
          den += am; }
        // p2: f0=v2.z f1=v2.w m=v3.x d0=v3.y d1=v3.z
        { float m = v3.x, am = fabsf(m), sc = m * am;
          float t0 = sc * v2.z, t1 = sc * v2.w;
          A  = fmaf(t1, v3.y, A);  Bm = fmaf(t0, v3.y, Bm);
          C  = fmaf(t1, v3.z, C);  D  = fmaf(t0, v3.z, D);
          E  = fmaf(am, fi, E);    F  = fmaf(am, fj0 + 2.f, F);
          den += am; }
        // p3: f0=v3.w f1=v4.x m=v4.y d0=v4.z d1=v4.w
        { float m = v4.y, am = fabsf(m), sc = m * am;
          float t0 = sc * v3.w, t1 = sc * v4.x;
          A  = fmaf(t1, v4.z, A);  Bm = fmaf(t0, v4.z, Bm);
          C  = fmaf(t1, v4.w, C);  D  = fmaf(t0, v4.w, D);
          E  = fmaf(am, fi, E);    F  = fmaf(am, fj0 + 3.f, F);
          den += am; }

        __syncthreads();                  // all threads done reading buf[st&1]
        if (st + 2 < n_stages) issue(st + 2);   // pipeline crosses chunk bounds
        cp_commit();

        // ---- per-chunk epilogue (40 KB still in flight -> DRAM stays busy) ----
        if ((st & 3) == 3) {
            float a = warp_red(A),  b = warp_red(Bm), c = warp_red(C),
                  d = warp_red(D),  e = warp_red(E),  f = warp_red(F),
                  dn = warp_red(den);
            int wid = t >> 5, lane = t & 31;
            if (lane == 0) {
                red[wid][0] = a; red[wid][1] = b; red[wid][2] = c;
                red[wid][3] = d; red[wid][4] = e; red[wid][5] = f;
                red[wid][6] = dn;
            }
            __syncthreads();
            if (t == 0) {
                float ra = 0.f, rb = 0.f, rc = 0.f, rd = 0.f,
                      re = 0.f, rf = 0.f, rdn = 0.f;
                #pragma unroll
                for (int w = 0; w < 8; ++w) {
                    ra += red[w][0]; rb += red[w][1]; rc += red[w][2];
                    rd += red[w][3]; re += red[w][4]; rf += red[w][5];
                    rdn += red[w][6];
                }
                float inv = 1.f / ((rdn == 0.f) ? 1.f : rdn);
                int ch = bid + (st >> 2) * grid;
                float* o = scratch + (size_t)ch * 5;
                o[0] = (ra + re) * inv;   // vf0
                o[1] = (rf - rb) * inv;   // vf1
                o[2] = (re - rc) * inv;   // vs0
                o[3] = (rd + rf) * inv;   // vs1
                o[4] = rdn;
            }
            __syncthreads();              // red[] reusable next chunk
            A = Bm = C = D = E = F = den = 0.f;
        }
    }

    // ---- block done: last block to finish assembles the output ----
    if (t == 0) {
        __threadfence();                  // all this block's scratch writes visible
        unsigned int old = atomicAdd(&g_count, 1u);
        s_last = (old == (unsigned)grid - 1u) ? 1 : 0;
    }
    __syncthreads();

    if (s_last) {
        if (t == 0) g_count = 0;          // reset for next graph replay
        __threadfence();
        const int B = total_chunks / N_PHAL;
        const int total = B * 42;
        for (int o = t; o < total; o += THREADS) {
            int c = o & 1;
            int r = (o >> 1) % 21;
            int b = o / 42;
            const float* sp = scratch + (size_t)b * N_PHAL * 5;

            float val;
            if (r == 0) {
                float acc = 0.f;
                #pragma unroll
                for (int k = 0; k < 5; ++k) {
                    int p = 4 * k;
                    float dn = __ldcg(sp + p * 5 + 4);
                    float vf = __ldcg(sp + p * 5 + c);
                    acc += (dn != 0.f) ? vf : 0.f;
                }
                val = acc * 0.2f;
            } else {
                int q  = r;                  // 1..20
                int iq = (q - 1) >> 2;
                int pq = 8 * iq + 4 - q;     // 4*iq + j_q
                int jq = pq - 4 * iq;
                int pn = min(pq + 1, N_PHAL - 1);
                float vs = __ldcg(sp + pq * 5 + 2 + c);
                if (jq == 3) val = vs;
                else         val = 0.5f * (vs + __ldcg(sp + pn * 5 + c));
            }
            out[o] = val;
        }
    }
}

extern "C" void kernel_launch(void* const* d_in, const int* in_sizes, int n_in,
                              void* d_out, int out_size)
{
    const float4* x = (const float4*)d_in[0];
    float* out = (float*)d_out;
    int B = in_sizes[0] / (N_PHAL * RES * RES * 5);   // 256
    int total_chunks = B * N_PHAL;                    // 5120

    float* scratch;
    cudaGetSymbolAddress((void**)&scratch, g_scratch);

    int grid = (total_chunks < GRID) ? total_chunks : GRID;
    fused_kernel<<<grid, THREADS>>>(x, scratch, out, total_chunks);
}